// round 16
// baseline (speedup 1.0000x reference)
#include <cuda_runtime.h>
#include <cuda_fp16.h>
#include <math.h>
#include <stdint.h>

#define BB 256
#define TT 256
#define HH 1024
#define VV 1024
#define G3H 3072
#define NBLK 148
#define NTHR 256
#define BH (BB * HH)
#define STAGE_BYTES 30720
#define DYN_SMEM (4 * STAGE_BYTES)

// ---------------- persistent device state ----------------
__device__ float g_h0f[2][BH];
__device__ float g_h1f[2][BH];
__device__ float g_pgi0[3L * BB * G3H];
__device__ float g_pgh0[3L * BB * G3H];
__device__ float g_pgi1[3L * BB * G3H];
__device__ float g_pgh1[3L * BB * G3H];
__device__ float g_pout[12L * BB * VV];

__device__ __align__(16) __half g_zs[2L * BB * 256];
__device__ __align__(16) __half g_zhs[2L * BH];
__device__ __align__(16) __half g_xcats[2L * BB * 512];
__device__ __align__(16) __half g_h0s[2][2L * BH];
__device__ __align__(16) __half g_h1s[2][2L * BH];
__device__ __align__(16) __half g_wz1s[2L * HH * 256];
__device__ __align__(16) __half g_wz2s[2L * 256 * HH];
__device__ __align__(16) __half g_wih0s[2L * G3H * 512];
__device__ __align__(16) __half g_whh0s[2L * G3H * HH];
__device__ __align__(16) __half g_wih1s[2L * G3H * HH];
__device__ __align__(16) __half g_whh1s[2L * G3H * HH];
__device__ __align__(16) __half g_wouts[2L * VV * HH];

// ---------------- launch-invariant grid barrier (proven R3) ----------------
__device__ unsigned g_count = 0;
__device__ unsigned g_gen = 0;

__device__ __forceinline__ void grid_sync() {
    __syncthreads();
    if (threadIdx.x == 0) {
        __threadfence();
        const unsigned snap = atomicAdd(&g_gen, 0u);
        const unsigned my = atomicAdd(&g_count, 1u);
        if (my == (unsigned)(gridDim.x - 1)) {
            atomicExch(&g_count, 0u);
            __threadfence();
            atomicAdd(&g_gen, 1u);
        } else {
            while (atomicAdd(&g_gen, 0u) == snap) { __nanosleep(64); }
        }
        __threadfence();
    }
    __syncthreads();
}

// ---------------- helpers ----------------
__device__ __forceinline__ uint32_t smem_u32(const void* p) {
    uint32_t a;
    asm("{ .reg .u64 t; cvta.to.shared.u64 t, %1; cvt.u32.u64 %0, t; }" : "=r"(a) : "l"(p));
    return a;
}
__device__ __forceinline__ void cpa16(uint32_t s, const void* g) {
    asm volatile("cp.async.cg.shared.global [%0], [%1], 16;" :: "r"(s), "l"(g));
}
#define CPA_COMMIT() asm volatile("cp.async.commit_group;" ::: "memory")
#define CPA_WAIT2()  asm volatile("cp.async.wait_group 2;" ::: "memory")

__device__ __forceinline__ void ldm4(uint32_t* r, uint32_t a) {
    asm volatile("ldmatrix.sync.aligned.m8n8.x4.shared.b16 {%0,%1,%2,%3}, [%4];"
                 : "=r"(r[0]), "=r"(r[1]), "=r"(r[2]), "=r"(r[3]) : "r"(a));
}
__device__ __forceinline__ void mma16816(float* c, const uint32_t* a, const uint32_t* b) {
    asm volatile(
        "mma.sync.aligned.m16n8k16.row.col.f32.f16.f16.f32 "
        "{%0,%1,%2,%3}, {%4,%5,%6,%7}, {%8,%9}, {%0,%1,%2,%3};"
        : "+f"(c[0]), "+f"(c[1]), "+f"(c[2]), "+f"(c[3])
        : "r"(a[0]), "r"(a[1]), "r"(a[2]), "r"(a[3]), "r"(b[0]), "r"(b[1]));
}

__device__ __forceinline__ float sigmoidf_(float x) { return 1.0f / (1.0f + expf(-x)); }
__device__ __forceinline__ float seluf_(float x) {
    const float sc = 1.0507009873554805f, al = 1.6732632423543772f;
    return x > 0.f ? sc * x : sc * al * expm1f(x);
}
__device__ __forceinline__ void split2(float a, __half& o0, __half& o1) {
    o0 = __float2half_rn(a);
    o1 = __float2half_rn(a - __half2float(o0));
}

// ---------------- HMMA unit: 128(M)x256(N) CTA tile, 8 warps of 64x64 ----------------
// terms: 0 -> a0*b0, 1 -> a0*b1, 2 -> a1*b0
struct MG {
    const __half* A; long aps;
    const __half* W; long wps;
    int K; int k32; int kSplit; int nSlices; int nTilesN; int N;
    float* P;
};

// Per stage: A 128x32 halfs (row stride 80B) at +0; B 256x32 at +10240.
// 256 threads: 2 A chunks + 4 B chunks of 16B each.
__device__ __forceinline__ void issue_stage(const __half* Ab, const __half* Wb, long K,
                                            int m0, int n0, int kidx, int stage,
                                            uint32_t sB) {
    const int tid = threadIdx.x;
    const uint32_t base = sB + stage * STAGE_BYTES;
    const long kof = (long)kidx * 32;
#pragma unroll
    for (int c = 0; c < 2; c++) {
        const int ch = tid * 2 + c;
        const int row = ch >> 2, seg = ch & 3;
        cpa16(base + row * 80 + seg * 16, Ab + (long)(m0 + row) * K + kof + seg * 8);
    }
#pragma unroll
    for (int c = 0; c < 4; c++) {
        const int ch = tid * 4 + c;
        const int row = ch >> 2, seg = ch & 3;
        cpa16(base + 10240 + row * 80 + seg * 16, Wb + (long)(n0 + row) * K + kof + seg * 8);
    }
}

__device__ void mma_unit(const MG& g, int m0, int n0, int slice, uint32_t sB) {
    const int tid = threadIdx.x, lane = tid & 31, wid = tid >> 5;
    const int wm = wid >> 2, wn = wid & 3;                 // 2x4 warp grid, 64x64 tiles
    const int term = slice % 3;
    const __half* Ab = g.A + (long)(term == 2 ? 1 : 0) * g.aps;
    const __half* Wb = g.W + (long)(term == 1 ? 1 : 0) * g.wps;
    const int nk = g.k32 / g.kSplit;
    const int k0 = (slice / 3) * nk;

    float acc[4][8][4];
#pragma unroll
    for (int i = 0; i < 4; i++)
#pragma unroll
        for (int j = 0; j < 8; j++)
#pragma unroll
            for (int c = 0; c < 4; c++) acc[i][j][c] = 0.f;

    // ldmatrix offsets (proven addressing from R7/R11/R14)
    const uint32_t abase =
        (uint32_t)(wm * 64 + ((lane >> 3) & 1) * 8 + (lane & 7)) * 80 + ((lane >> 4) << 4);
    const uint32_t wbase = 10240u +
        (uint32_t)(wn * 64 + ((lane >> 4) << 3) + (lane & 7)) * 80 + (((lane >> 3) & 1) << 4);

    issue_stage(Ab, Wb, g.K, m0, n0, k0 + 0, 0, sB); CPA_COMMIT();
    issue_stage(Ab, Wb, g.K, m0, n0, k0 + 1, 1, sB); CPA_COMMIT();
    issue_stage(Ab, Wb, g.K, m0, n0, k0 + 2, 2, sB); CPA_COMMIT();

    for (int it = 0; it < nk; it++) {
        CPA_WAIT2();
        __syncthreads();
        if (it + 3 < nk)
            issue_stage(Ab, Wb, g.K, m0, n0, k0 + it + 3, (it + 3) & 3, sB);
        CPA_COMMIT();
        const uint32_t stg = sB + (it & 3) * STAGE_BYTES;
#pragma unroll
        for (int s = 0; s < 2; s++) {
            uint32_t af[4][4], bf[4][4];
#pragma unroll
            for (int mt = 0; mt < 4; mt++) ldm4(af[mt], stg + abase + mt * (16 * 80) + s * 32);
#pragma unroll
            for (int nb = 0; nb < 4; nb++) ldm4(bf[nb], stg + wbase + nb * (16 * 80) + s * 32);
#pragma unroll
            for (int mt = 0; mt < 4; mt++)
#pragma unroll
                for (int nb = 0; nb < 4; nb++) {
                    mma16816(acc[mt][nb * 2], af[mt], bf[nb]);
                    mma16816(acc[mt][nb * 2 + 1], af[mt], bf[nb] + 2);
                }
        }
    }

    float* P = g.P + (long)slice * BB * g.N;
#pragma unroll
    for (int mt = 0; mt < 4; mt++)
#pragma unroll
        for (int nt = 0; nt < 8; nt++) {
            const int m = m0 + wm * 64 + mt * 16 + (lane >> 2);
            const int n = n0 + wn * 64 + nt * 8 + (lane & 3) * 2;
            *(float2*)(P + (long)m * g.N + n) = make_float2(acc[mt][nt][0], acc[mt][nt][1]);
            *(float2*)(P + (long)(m + 8) * g.N + n) = make_float2(acc[mt][nt][2], acc[mt][nt][3]);
        }
    __syncthreads();
}

__device__ void run_units(const MG& ga, const MG* gb, uint32_t sB) {
    const int na = 2 * ga.nTilesN * ga.nSlices;
    const int nb = gb ? 2 * gb->nTilesN * gb->nSlices : 0;
    for (int u = blockIdx.x; u < na + nb; u += gridDim.x) {
        const MG& g = (u < na) ? ga : *gb;
        const int v = (u < na) ? u : u - na;
        const int slice = v % g.nSlices;
        const int tile = v / g.nSlices;
        mma_unit(g, (tile / g.nTilesN) * 128, (tile % g.nTilesN) * 256, slice, sB);
    }
}

// ---------------- elementwise phases ----------------
__device__ void split_mat(const float* w, __half* d, long n) {
    const long st = (long)gridDim.x * blockDim.x;
    for (long i = (long)blockIdx.x * blockDim.x + threadIdx.x; i < n; i += st) {
        __half s0, s1; split2(w[i], s0, s1);
        d[i] = s0; d[n + i] = s1;
    }
}

__device__ void combine_gru(const float* pgi, const float* pgh,
                            const float* bih, const float* bhh,
                            const float* hp, float* hn, __half* hs) {
    const long S = (long)BB * G3H;
    for (int i = blockIdx.x * blockDim.x + threadIdx.x; i < BH; i += gridDim.x * blockDim.x) {
        const int b = i >> 10, j = i & 1023;
        const long r0 = (long)b * G3H + j, z0 = r0 + HH, n0 = r0 + 2 * HH;
        const float gir = pgi[r0] + pgi[S + r0] + pgi[2 * S + r0] + bih[j];
        const float giz = pgi[z0] + pgi[S + z0] + pgi[2 * S + z0] + bih[HH + j];
        const float gin = pgi[n0] + pgi[S + n0] + pgi[2 * S + n0] + bih[2 * HH + j];
        const float ghr = pgh[r0] + pgh[S + r0] + pgh[2 * S + r0] + bhh[j];
        const float ghz = pgh[z0] + pgh[S + z0] + pgh[2 * S + z0] + bhh[HH + j];
        const float ghn = pgh[n0] + pgh[S + n0] + pgh[2 * S + n0] + bhh[2 * HH + j];
        const float r = sigmoidf_(gir + ghr);
        const float zg = sigmoidf_(giz + ghz);
        const float n = tanhf(gin + r * ghn);
        const float v = (1.0f - zg) * n + zg * hp[i];
        hn[i] = v;
        __half s0, s1; split2(v, s0, s1);
        hs[i] = s0; hs[BH + i] = s1;
    }
}

__device__ void argmax_phase(const float* bout, float* out, const float* emb,
                             float* samples, int t, float* sv, int* si) {
    const long S = (long)BB * VV;
    const int tid = threadIdx.x;
    for (int b = blockIdx.x; b < BB; b += gridDim.x) {
        const float* pb = g_pout + (long)b * VV;
        float* orow = out + (long)b * TT * VV + (long)t * VV;
        float best = -1e30f; int bidx = VV;
        for (int j = tid; j < VV; j += NTHR) {
            float v = bout[j];
#pragma unroll
            for (int s = 0; s < 12; s++) v += pb[s * S + j];
            v = fmaxf(v, 0.f);
            orow[j] = v;
            if (v > best) { best = v; bidx = j; }
        }
        sv[tid] = best; si[tid] = bidx;
        __syncthreads();
        for (int s = NTHR / 2; s > 0; s >>= 1) {
            if (tid < s) {
                const float v2 = sv[tid + s]; const int i2 = si[tid + s];
                if (v2 > sv[tid] || (v2 == sv[tid] && i2 < si[tid])) { sv[tid] = v2; si[tid] = i2; }
            }
            __syncthreads();
        }
        const int idx = si[0];
        __syncthreads();
        for (int jj = tid; jj < 256; jj += NTHR) {
            __half s0, s1;
            split2(emb[(long)idx * 256 + jj], s0, s1);
            __half* xc = g_xcats + (long)b * 512 + jj;
            xc[0] = s0; xc[131072] = s1;
        }
        if (tid == 0 && samples) samples[(long)b * TT + t] = (float)idx;
        __syncthreads();
    }
}

// ---------------- the whole decoder, ONE persistent kernel ----------------
__global__ void __launch_bounds__(NTHR, 1) srdec(
    const float* z, const float* emb, const float* x0,
    const float* w_z1, const float* b_z1, const float* w_z2, const float* b_z2,
    const float* w_ih0, const float* w_hh0, const float* b_ih0, const float* b_hh0,
    const float* w_ih1, const float* w_hh1, const float* b_ih1, const float* b_hh1,
    const float* w_out, const float* b_out, float* out, float* samples) {

    extern __shared__ __align__(16) uint8_t dyn[];
    __shared__ float sv[NTHR];
    __shared__ int si[NTHR];
    const uint32_t sB = smem_u32(dyn);
    const int tid = threadIdx.x;
    const int gst = gridDim.x * blockDim.x;

    // ---- P1: init state + split weights/z ----
    {
        const __half zh16 = __float2half(0.f);
        for (int i = blockIdx.x * blockDim.x + tid; i < BH; i += gst) {
            g_h0f[0][i] = 0.f; g_h1f[0][i] = 0.f;
            g_h0s[0][i] = zh16; g_h0s[0][BH + i] = zh16;
            g_h1s[0][i] = zh16; g_h1s[0][BH + i] = zh16;
        }
        for (int i = blockIdx.x * blockDim.x + tid; i < BB * 256; i += gst) {
            const int b = i >> 8, k = i & 255;
            __half s0, s1; split2(x0[k], s0, s1);
            __half* xc = g_xcats + (long)b * 512 + k;
            xc[0] = s0; xc[131072] = s1;
        }
        split_mat(z, g_zs, (long)BB * 256);
        split_mat(w_z1, g_wz1s, (long)HH * 256);
        split_mat(w_z2, g_wz2s, (long)256 * HH);
        split_mat(w_ih0, g_wih0s, (long)G3H * 512);
        split_mat(w_hh0, g_whh0s, (long)G3H * HH);
        split_mat(w_ih1, g_wih1s, (long)G3H * HH);
        split_mat(w_hh1, g_whh1s, (long)G3H * HH);
        split_mat(w_out, g_wouts, (long)VV * HH);
    }
    grid_sync();

    // ---- P2: zh_raw = z @ w_z1^T (3 partials) ----
    {
        MG s = { g_zs, (long)BB * 256, g_wz1s, (long)HH * 256,
                 256, 8, 1, 3, 4, 1024, g_pgi0 };
        run_units(s, nullptr, sB);
    }
    grid_sync();
    // ---- P3: zh = selu(sum + b_z1), split ----
    for (int i = blockIdx.x * blockDim.x + tid; i < BH; i += gst) {
        const int j = i & 1023;
        const float v = seluf_(g_pgi0[i] + g_pgi0[BH + i] + g_pgi0[2 * BH + i] + b_z1[j]);
        __half s0, s1; split2(v, s0, s1);
        g_zhs[i] = s0; g_zhs[BH + i] = s1;
    }
    grid_sync();
    // ---- P4: zemb partials ----
    {
        MG s = { g_zhs, (long)BH, g_wz2s, (long)256 * HH,
                 1024, 32, 1, 3, 1, 256, g_pgi0 };
        run_units(s, nullptr, sB);
    }
    grid_sync();
    // ---- P5: zemb combine -> xcat[:,256:512] ----
    for (int i = blockIdx.x * blockDim.x + tid; i < BB * 256; i += gst) {
        const int b = i >> 8, k = i & 255;
        const float v = g_pgi0[i] + g_pgi0[65536 + i] + g_pgi0[131072 + i] + b_z2[k];
        __half s0, s1; split2(v, s0, s1);
        __half* xc = g_xcats + (long)b * 512 + 256 + k;
        xc[0] = s0; xc[131072] = s1;
    }
    grid_sync();

    for (int t = 0; t < TT; t++) {
        const int r = t & 1, w = r ^ 1;

        {   // layer 0 gates: 72 + 72 units (single wave on 148 CTAs)
            MG gi = { g_xcats, 131072L, g_wih0s, (long)G3H * 512,
                      512, 16, 1, 3, 12, G3H, g_pgi0 };
            MG gh = { g_h0s[r], (long)BH, g_whh0s, (long)G3H * HH,
                      1024, 32, 1, 3, 12, G3H, g_pgh0 };
            run_units(gi, &gh, sB);
        }
        grid_sync();
        combine_gru(g_pgi0, g_pgh0, b_ih0, b_hh0, g_h0f[r], g_h0f[w], g_h0s[w]);
        grid_sync();

        {   // layer 1 gates
            MG gi = { g_h0s[w], (long)BH, g_wih1s, (long)G3H * HH,
                      1024, 32, 1, 3, 12, G3H, g_pgi1 };
            MG gh = { g_h1s[r], (long)BH, g_whh1s, (long)G3H * HH,
                      1024, 32, 1, 3, 12, G3H, g_pgh1 };
            run_units(gi, &gh, sB);
        }
        grid_sync();
        combine_gru(g_pgi1, g_pgh1, b_ih1, b_hh1, g_h1f[r], g_h1f[w], g_h1s[w]);
        grid_sync();

        {   // output logits partials: 12 slices = 3 terms x 4 K-quarters -> 96 units
            MG s = { g_h1s[w], (long)BH, g_wouts, (long)VV * HH,
                     1024, 32, 4, 12, 4, VV, g_pout };
            run_units(s, nullptr, sB);
        }
        grid_sync();

        argmax_phase(b_out, out, emb, samples, t, sv, si);
        grid_sync();
    }
}

extern "C" void kernel_launch(void* const* d_in, const int* in_sizes, int n_in,
                              void* d_out, int out_size) {
    const float* z     = (const float*)d_in[0];
    const float* emb   = (const float*)d_in[3];
    const float* x0    = (const float*)d_in[4];
    const float* w_z1  = (const float*)d_in[5];
    const float* b_z1  = (const float*)d_in[6];
    const float* w_z2  = (const float*)d_in[7];
    const float* b_z2  = (const float*)d_in[8];
    const float* w_ih0 = (const float*)d_in[9];
    const float* w_hh0 = (const float*)d_in[10];
    const float* b_ih0 = (const float*)d_in[11];
    const float* b_hh0 = (const float*)d_in[12];
    const float* w_ih1 = (const float*)d_in[13];
    const float* w_hh1 = (const float*)d_in[14];
    const float* b_ih1 = (const float*)d_in[15];
    const float* b_hh1 = (const float*)d_in[16];
    const float* w_out = (const float*)d_in[17];
    const float* b_out = (const float*)d_in[18];
    float* out = (float*)d_out;

    const long BTV = (long)BB * TT * VV;
    float* samples_base = ((long)out_size >= BTV + (long)BB * TT) ? (out + BTV) : nullptr;

    cudaFuncSetAttribute(srdec, cudaFuncAttributeMaxDynamicSharedMemorySize, DYN_SMEM);
    srdec<<<NBLK, NTHR, DYN_SMEM>>>(
        z, emb, x0, w_z1, b_z1, w_z2, b_z2,
        w_ih0, w_hh0, b_ih0, b_hh0, w_ih1, w_hh1, b_ih1, b_hh1,
        w_out, b_out, out, samples_base);
}

// round 17
// speedup vs baseline: 1.3124x; 1.3124x over previous
#include <cuda_runtime.h>
#include <cuda_fp16.h>
#include <math.h>
#include <stdint.h>

#define BB 256
#define TT 256
#define HH 1024
#define VV 1024
#define G3H 3072
#define NBLK 148
#define NTHR 512
#define BH (BB * HH)
#define STAGE64 40960
#define DYN_SMEM (3 * STAGE64)

// ---------------- persistent device state ----------------
__device__ float g_h0f[2][BH];
__device__ float g_h1f[2][BH];
__device__ float g_pgi[3L * BB * G3H];   // shared by layer0/layer1 (reused)
__device__ float g_pgh[3L * BB * G3H];
__device__ float g_pout[6L * BB * VV];

__device__ __align__(16) __half g_zs[2L * BB * 256];
__device__ __align__(16) __half g_zhs[2L * BH];
__device__ __align__(16) __half g_xcats[2L * BB * 512];
__device__ __align__(16) __half g_h0s[2][2L * BH];
__device__ __align__(16) __half g_h1s[2][2L * BH];
__device__ __align__(16) __half g_wz1s[2L * HH * 256];
__device__ __align__(16) __half g_wz2s[2L * 256 * HH];
__device__ __align__(16) __half g_wih0s[2L * G3H * 512];
__device__ __align__(16) __half g_whh0s[2L * G3H * HH];
__device__ __align__(16) __half g_wih1s[2L * G3H * HH];
__device__ __align__(16) __half g_whh1s[2L * G3H * HH];
__device__ __align__(16) __half g_wouts[2L * VV * HH];

// ---------------- launch-invariant grid barrier ----------------
__device__ unsigned g_count = 0;
__device__ unsigned g_gen = 0;

__device__ __forceinline__ void grid_sync() {
    __syncthreads();
    if (threadIdx.x == 0) {
        __threadfence();
        const unsigned snap = ((volatile unsigned*)&g_gen)[0];
        const unsigned my = atomicAdd(&g_count, 1u);
        if (my == (unsigned)(gridDim.x - 1)) {
            atomicExch(&g_count, 0u);
            __threadfence();
            atomicAdd(&g_gen, 1u);
        } else {
            while (((volatile unsigned*)&g_gen)[0] == snap) { __nanosleep(32); }
        }
        __threadfence();
    }
    __syncthreads();
}

// ---------------- helpers ----------------
__device__ __forceinline__ uint32_t smem_u32(const void* p) {
    uint32_t a;
    asm("{ .reg .u64 t; cvta.to.shared.u64 t, %1; cvt.u32.u64 %0, t; }" : "=r"(a) : "l"(p));
    return a;
}
__device__ __forceinline__ void cpa16(uint32_t s, const void* g) {
    asm volatile("cp.async.cg.shared.global [%0], [%1], 16;" :: "r"(s), "l"(g));
}
#define CPA_COMMIT() asm volatile("cp.async.commit_group;" ::: "memory")
#define CPA_WAIT1()  asm volatile("cp.async.wait_group 1;" ::: "memory")

__device__ __forceinline__ void ldm4(uint32_t* r, uint32_t a) {
    asm volatile("ldmatrix.sync.aligned.m8n8.x4.shared.b16 {%0,%1,%2,%3}, [%4];"
                 : "=r"(r[0]), "=r"(r[1]), "=r"(r[2]), "=r"(r[3]) : "r"(a));
}
__device__ __forceinline__ void mma16816(float* c, const uint32_t* a, const uint32_t* b) {
    asm volatile(
        "mma.sync.aligned.m16n8k16.row.col.f32.f16.f16.f32 "
        "{%0,%1,%2,%3}, {%4,%5,%6,%7}, {%8,%9}, {%0,%1,%2,%3};"
        : "+f"(c[0]), "+f"(c[1]), "+f"(c[2]), "+f"(c[3])
        : "r"(a[0]), "r"(a[1]), "r"(a[2]), "r"(a[3]), "r"(b[0]), "r"(b[1]));
}

__device__ __forceinline__ float sigmoidf_(float x) { return 1.0f / (1.0f + expf(-x)); }
__device__ __forceinline__ float seluf_(float x) {
    const float sc = 1.0507009873554805f, al = 1.6732632423543772f;
    return x > 0.f ? sc * x : sc * al * expm1f(x);
}
__device__ __forceinline__ void split2(float a, __half& o0, __half& o1) {
    o0 = __float2half_rn(a);
    o1 = __float2half_rn(a - __half2float(o0));
}

// ---------------- HMMA unit: 128x128 tile, 16 warps of 32x32, k64 mainloop ----------------
// terms: 0 -> a0*b0, 1 -> a0*b1, 2 -> a1*b0
struct MG {
    const __half* A; long aps;
    const __half* W; long wps;
    int K; int k32; int kSplit; int nSlices; int nTilesN; int N;
    float* P;
};

// Stage (40960B) = 2 sub-blocks of 20480B; sub = A(128x32h, 80B rows) at +0, W at +10240.
// 512 threads: per sub each thread copies one 16B A chunk + one 16B W chunk.
__device__ __forceinline__ void issue_stage64(const __half* Ab, const __half* Wb, long K,
                                              int m0, int n0, int k64, int stage,
                                              uint32_t sB) {
    const int tid = threadIdx.x;
    const int row = tid >> 2, seg = tid & 3;
    const uint32_t rb = (uint32_t)row * 80 + seg * 16;
    const long ga = (long)(m0 + row) * K + seg * 8;
    const long gw = (long)(n0 + row) * K + seg * 8;
    const uint32_t base = sB + stage * STAGE64;
#pragma unroll
    for (int sub = 0; sub < 2; sub++) {
        const long kof = (long)(k64 * 2 + sub) * 32;
        cpa16(base + sub * 20480 + rb, Ab + ga + kof);
        cpa16(base + sub * 20480 + 10240 + rb, Wb + gw + kof);
    }
}

__device__ void mma_unit(const MG& g, int m0, int n0, int slice, uint32_t sB) {
    const int tid = threadIdx.x, lane = tid & 31, wid = tid >> 5;
    const int wm = wid >> 2, wn = wid & 3;                 // 4x4 warp grid, 32x32 tiles
    const int term = slice % 3;
    const __half* Ab = g.A + (long)(term == 2 ? 1 : 0) * g.aps;
    const __half* Wb = g.W + (long)(term == 1 ? 1 : 0) * g.wps;
    const int nk64 = (g.k32 / g.kSplit) >> 1;
    const int k0 = (slice / 3) * nk64;

    float acc[2][4][4];
#pragma unroll
    for (int i = 0; i < 2; i++)
#pragma unroll
        for (int j = 0; j < 4; j++)
#pragma unroll
            for (int c = 0; c < 4; c++) acc[i][j][c] = 0.f;

    const uint32_t aoff =
        (uint32_t)(wm * 32 + ((lane >> 3) & 1) * 8 + (lane & 7)) * 80 + ((lane >> 4) << 4);
    const uint32_t woff = 10240u +
        (uint32_t)(wn * 32 + ((lane >> 4) << 3) + (lane & 7)) * 80 + (((lane >> 3) & 1) << 4);

    issue_stage64(Ab, Wb, g.K, m0, n0, k0 + 0, 0, sB); CPA_COMMIT();
    issue_stage64(Ab, Wb, g.K, m0, n0, k0 + 1, 1, sB); CPA_COMMIT();

    for (int it = 0; it < nk64; it++) {
        CPA_WAIT1();
        __syncthreads();
        int st = it % 3;
        if (it + 2 < nk64) {
            int ns = it + 2 - ((it + 2) / 3) * 3;
            issue_stage64(Ab, Wb, g.K, m0, n0, k0 + it + 2, ns, sB);
        }
        CPA_COMMIT();
        const uint32_t stg = sB + st * STAGE64;
#pragma unroll
        for (int sub = 0; sub < 2; sub++) {
            const uint32_t sbb = stg + sub * 20480;
#pragma unroll
            for (int s = 0; s < 2; s++) {
                uint32_t af[2][4], b0[4], b1[4];
                ldm4(af[0], sbb + aoff + s * 32);
                ldm4(af[1], sbb + aoff + 16 * 80 + s * 32);
                ldm4(b0, sbb + woff + s * 32);
                ldm4(b1, sbb + woff + 16 * 80 + s * 32);
#pragma unroll
                for (int mt = 0; mt < 2; mt++) {
                    mma16816(acc[mt][0], af[mt], b0);
                    mma16816(acc[mt][1], af[mt], b0 + 2);
                    mma16816(acc[mt][2], af[mt], b1);
                    mma16816(acc[mt][3], af[mt], b1 + 2);
                }
            }
        }
    }

    float* P = g.P + (long)slice * BB * g.N;
#pragma unroll
    for (int mt = 0; mt < 2; mt++)
#pragma unroll
        for (int nt = 0; nt < 4; nt++) {
            const int m = m0 + wm * 32 + mt * 16 + (lane >> 2);
            const int n = n0 + wn * 32 + nt * 8 + (lane & 3) * 2;
            *(float2*)(P + (long)m * g.N + n) = make_float2(acc[mt][nt][0], acc[mt][nt][1]);
            *(float2*)(P + (long)(m + 8) * g.N + n) = make_float2(acc[mt][nt][2], acc[mt][nt][3]);
        }
    __syncthreads();
}

__device__ void run_units(const MG& ga, const MG* gb, uint32_t sB) {
    const int na = 2 * ga.nTilesN * ga.nSlices;
    const int nb = gb ? 2 * gb->nTilesN * gb->nSlices : 0;
    for (int u = blockIdx.x; u < na + nb; u += gridDim.x) {
        const MG& g = (u < na) ? ga : *gb;
        const int v = (u < na) ? u : u - na;
        const int slice = v % g.nSlices;
        const int tile = v / g.nSlices;
        mma_unit(g, (tile / g.nTilesN) * 128, (tile % g.nTilesN) * 128, slice, sB);
    }
}

// ---------------- elementwise phases ----------------
__device__ void split_mat(const float* w, __half* d, long n) {
    const long st = (long)gridDim.x * blockDim.x;
    for (long i = (long)blockIdx.x * blockDim.x + threadIdx.x; i < n; i += st) {
        __half s0, s1; split2(w[i], s0, s1);
        d[i] = s0; d[n + i] = s1;
    }
}

__device__ void combine_gru(const float* pgi, const float* pgh,
                            const float* bih, const float* bhh,
                            const float* hp, float* hn, __half* hs) {
    const long S = (long)BB * G3H;
    for (int i = blockIdx.x * blockDim.x + threadIdx.x; i < BH; i += gridDim.x * blockDim.x) {
        const int b = i >> 10, j = i & 1023;
        const long r0 = (long)b * G3H + j, z0 = r0 + HH, n0 = r0 + 2 * HH;
        const float gir = pgi[r0] + pgi[S + r0] + pgi[2 * S + r0] + bih[j];
        const float giz = pgi[z0] + pgi[S + z0] + pgi[2 * S + z0] + bih[HH + j];
        const float gin = pgi[n0] + pgi[S + n0] + pgi[2 * S + n0] + bih[2 * HH + j];
        const float ghr = pgh[r0] + pgh[S + r0] + pgh[2 * S + r0] + bhh[j];
        const float ghz = pgh[z0] + pgh[S + z0] + pgh[2 * S + z0] + bhh[HH + j];
        const float ghn = pgh[n0] + pgh[S + n0] + pgh[2 * S + n0] + bhh[2 * HH + j];
        const float r = sigmoidf_(gir + ghr);
        const float zg = sigmoidf_(giz + ghz);
        const float n = tanhf(gin + r * ghn);
        const float v = (1.0f - zg) * n + zg * hp[i];
        hn[i] = v;
        __half s0, s1; split2(v, s0, s1);
        hs[i] = s0; hs[BH + i] = s1;
    }
}

__device__ void argmax_phase(const float* bout, float* out, const float* emb,
                             float* samples, int t, float* sv, int* si) {
    const long S = (long)BB * VV;
    const int tid = threadIdx.x;
    for (int b = blockIdx.x; b < BB; b += gridDim.x) {
        const float* pb = g_pout + (long)b * VV;
        float* orow = out + (long)b * TT * VV + (long)t * VV;
        float best = -1e30f; int bidx = VV;
        for (int j = tid; j < VV; j += NTHR) {
            float v = pb[j] + pb[S + j] + pb[2 * S + j] + pb[3 * S + j] +
                      pb[4 * S + j] + pb[5 * S + j] + bout[j];
            v = fmaxf(v, 0.f);
            __stcs(&orow[j], v);
            if (v > best) { best = v; bidx = j; }
        }
        sv[tid] = best; si[tid] = bidx;
        __syncthreads();
        for (int s = NTHR / 2; s > 0; s >>= 1) {
            if (tid < s) {
                const float v2 = sv[tid + s]; const int i2 = si[tid + s];
                if (v2 > sv[tid] || (v2 == sv[tid] && i2 < si[tid])) { sv[tid] = v2; si[tid] = i2; }
            }
            __syncthreads();
        }
        const int idx = si[0];
        __syncthreads();
        for (int jj = tid; jj < 256; jj += NTHR) {
            __half s0, s1;
            split2(emb[(long)idx * 256 + jj], s0, s1);
            __half* xc = g_xcats + (long)b * 512 + jj;
            xc[0] = s0; xc[131072] = s1;
        }
        if (tid == 0 && samples) samples[(long)b * TT + t] = (float)idx;
        __syncthreads();
    }
}

// ---------------- the whole decoder, ONE persistent kernel ----------------
__global__ void __launch_bounds__(NTHR, 1) srdec(
    const float* z, const float* emb, const float* x0,
    const float* w_z1, const float* b_z1, const float* w_z2, const float* b_z2,
    const float* w_ih0, const float* w_hh0, const float* b_ih0, const float* b_hh0,
    const float* w_ih1, const float* w_hh1, const float* b_ih1, const float* b_hh1,
    const float* w_out, const float* b_out, float* out, float* samples) {

    extern __shared__ __align__(16) uint8_t dyn[];
    __shared__ float sv[NTHR];
    __shared__ int si[NTHR];
    const uint32_t sB = smem_u32(dyn);
    const int tid = threadIdx.x;
    const int gst = gridDim.x * blockDim.x;

    // ---- P1: init state + split weights/z ----
    {
        const __half zh16 = __float2half(0.f);
        for (int i = blockIdx.x * blockDim.x + tid; i < BH; i += gst) {
            g_h0f[0][i] = 0.f; g_h1f[0][i] = 0.f;
            g_h0s[0][i] = zh16; g_h0s[0][BH + i] = zh16;
            g_h1s[0][i] = zh16; g_h1s[0][BH + i] = zh16;
        }
        for (int i = blockIdx.x * blockDim.x + tid; i < BB * 256; i += gst) {
            const int b = i >> 8, k = i & 255;
            __half s0, s1; split2(x0[k], s0, s1);
            __half* xc = g_xcats + (long)b * 512 + k;
            xc[0] = s0; xc[131072] = s1;
        }
        split_mat(z, g_zs, (long)BB * 256);
        split_mat(w_z1, g_wz1s, (long)HH * 256);
        split_mat(w_z2, g_wz2s, (long)256 * HH);
        split_mat(w_ih0, g_wih0s, (long)G3H * 512);
        split_mat(w_hh0, g_whh0s, (long)G3H * HH);
        split_mat(w_ih1, g_wih1s, (long)G3H * HH);
        split_mat(w_hh1, g_whh1s, (long)G3H * HH);
        split_mat(w_out, g_wouts, (long)VV * HH);
    }
    grid_sync();

    // ---- P2: zh_raw = z @ w_z1^T (3 partials) ----
    {
        MG s = { g_zs, (long)BB * 256, g_wz1s, (long)HH * 256,
                 256, 8, 1, 3, 8, 1024, g_pgi };
        run_units(s, nullptr, sB);
    }
    grid_sync();
    // ---- P3: zh = selu(sum + b_z1), split ----
    for (int i = blockIdx.x * blockDim.x + tid; i < BH; i += gst) {
        const int j = i & 1023;
        const float v = seluf_(g_pgi[i] + g_pgi[BH + i] + g_pgi[2 * BH + i] + b_z1[j]);
        __half s0, s1; split2(v, s0, s1);
        g_zhs[i] = s0; g_zhs[BH + i] = s1;
    }
    grid_sync();
    // ---- P4: zemb partials ----
    {
        MG s = { g_zhs, (long)BH, g_wz2s, (long)256 * HH,
                 1024, 32, 1, 3, 2, 256, g_pgi };
        run_units(s, nullptr, sB);
    }
    grid_sync();
    // ---- P5: zemb combine -> xcat[:,256:512] ----
    for (int i = blockIdx.x * blockDim.x + tid; i < BB * 256; i += gst) {
        const int b = i >> 8, k = i & 255;
        const float v = g_pgi[i] + g_pgi[65536 + i] + g_pgi[131072 + i] + b_z2[k];
        __half s0, s1; split2(v, s0, s1);
        __half* xc = g_xcats + (long)b * 512 + 256 + k;
        xc[0] = s0; xc[131072] = s1;
    }
    grid_sync();

    for (int t = 0; t < TT; t++) {
        const int r = t & 1, w = r ^ 1;

        {   // layer 0 gates
            MG gi = { g_xcats, 131072L, g_wih0s, (long)G3H * 512,
                      512, 16, 1, 3, 24, G3H, g_pgi };
            MG gh = { g_h0s[r], (long)BH, g_whh0s, (long)G3H * HH,
                      1024, 32, 1, 3, 24, G3H, g_pgh };
            run_units(gi, &gh, sB);
        }
        grid_sync();
        combine_gru(g_pgi, g_pgh, b_ih0, b_hh0, g_h0f[r], g_h0f[w], g_h0s[w]);
        grid_sync();

        {   // layer 1 gates (reuse same partial buffers)
            MG gi = { g_h0s[w], (long)BH, g_wih1s, (long)G3H * HH,
                      1024, 32, 1, 3, 24, G3H, g_pgi };
            MG gh = { g_h1s[r], (long)BH, g_whh1s, (long)G3H * HH,
                      1024, 32, 1, 3, 24, G3H, g_pgh };
            run_units(gi, &gh, sB);
        }
        grid_sync();
        combine_gru(g_pgi, g_pgh, b_ih1, b_hh1, g_h1f[r], g_h1f[w], g_h1s[w]);
        grid_sync();

        {   // output logits partials: 6 slices = 3 terms x 2 K-halves -> 96 units
            MG s = { g_h1s[w], (long)BH, g_wouts, (long)VV * HH,
                     1024, 32, 2, 6, 8, VV, g_pout };
            run_units(s, nullptr, sB);
        }
        grid_sync();

        argmax_phase(b_out, out, emb, samples, t, sv, si);
        grid_sync();
    }
}

extern "C" void kernel_launch(void* const* d_in, const int* in_sizes, int n_in,
                              void* d_out, int out_size) {
    const float* z     = (const float*)d_in[0];
    const float* emb   = (const float*)d_in[3];
    const float* x0    = (const float*)d_in[4];
    const float* w_z1  = (const float*)d_in[5];
    const float* b_z1  = (const float*)d_in[6];
    const float* w_z2  = (const float*)d_in[7];
    const float* b_z2  = (const float*)d_in[8];
    const float* w_ih0 = (const float*)d_in[9];
    const float* w_hh0 = (const float*)d_in[10];
    const float* b_ih0 = (const float*)d_in[11];
    const float* b_hh0 = (const float*)d_in[12];
    const float* w_ih1 = (const float*)d_in[13];
    const float* w_hh1 = (const float*)d_in[14];
    const float* b_ih1 = (const float*)d_in[15];
    const float* b_hh1 = (const float*)d_in[16];
    const float* w_out = (const float*)d_in[17];
    const float* b_out = (const float*)d_in[18];
    float* out = (float*)d_out;

    const long BTV = (long)BB * TT * VV;
    float* samples_base = ((long)out_size >= BTV + (long)BB * TT) ? (out + BTV) : nullptr;

    cudaFuncSetAttribute(srdec, cudaFuncAttributeMaxDynamicSharedMemorySize, DYN_SMEM);
    srdec<<<NBLK, NTHR, DYN_SMEM>>>(
        z, emb, x0, w_z1, b_z1, w_z2, b_z2,
        w_ih0, w_hh0, b_ih0, b_hh0, w_ih1, w_hh1, b_ih1, b_hh1,
        w_out, b_out, out, samples_base);
}